// round 12
// baseline (speedup 1.0000x reference)
#include <cuda_runtime.h>
#include <cuda.h>
#include <cuda_bf16.h>
#include <cstdint>

// tcgen05 exists only in the compute_103a pass; plain sm_103 compiles empty stubs.
#if defined(__CUDA_ARCH__) && defined(__CUDA_ARCH_FEAT_SM103_ALL)
#define HAS_TC 1
#else
#define HAS_TC 0
#endif

constexpr int Bb = 32, Np = 512, Dd = 512;

// ---------------- scratch (__device__ globals; alloc-free rule) -------------
__device__ __align__(1024) __nv_bfloat16 g_xhi [(size_t)Bb * Np * Dd];
__device__ __align__(1024) __nv_bfloat16 g_xlo [(size_t)Bb * Np * Dd];
__device__ __align__(1024) __nv_bfloat16 g_wthi[(size_t)Dd * Dd];
__device__ __align__(1024) __nv_bfloat16 g_wtlo[(size_t)Dd * Dd];
__device__ __align__(1024) __nv_bfloat16 g_xwhi[(size_t)Bb * Np * Dd];
__device__ __align__(1024) __nv_bfloat16 g_xwlo[(size_t)Bb * Np * Dd];

// ---------------- common helpers -------------------------------------------
__device__ __forceinline__ uint32_t smem_u32(const void* p) {
    uint32_t a;
    asm("{ .reg .u64 t; cvta.to.shared.u64 t, %1; cvt.u32.u64 %0, t; }"
        : "=r"(a) : "l"(p));
    return a;
}

// ---------------- conversion kernels ---------------------------------------
__global__ __launch_bounds__(256) void conv_x_kernel(const float4* __restrict__ X) {
    size_t i = (size_t)blockIdx.x * 256 + threadIdx.x;
    float4 v = X[i];
    union { __nv_bfloat16 b[4]; uint2 u; } H, L;
    const float* f = &v.x;
    #pragma unroll
    for (int j = 0; j < 4; j++) {
        __nv_bfloat16 h = __float2bfloat16_rn(f[j]);
        H.b[j] = h;
        L.b[j] = __float2bfloat16_rn(f[j] - __bfloat162float(h));
    }
    reinterpret_cast<uint2*>(g_xhi)[i] = H.u;
    reinterpret_cast<uint2*>(g_xlo)[i] = L.u;
}

__global__ __launch_bounds__(256) void conv_w_kernel(const float* __restrict__ W) {
    __shared__ float t[32][33];
    int tx = threadIdx.x, ty = threadIdx.y;          // 32 x 8
    int bx = blockIdx.x * 32, by = blockIdx.y * 32;  // bx: n-block, by: k-block
    #pragma unroll
    for (int r = 0; r < 4; r++)
        t[ty + r * 8][tx] = W[(size_t)(by + ty + r * 8) * Dd + bx + tx];
    __syncthreads();
    #pragma unroll
    for (int r = 0; r < 4; r++) {
        int n = bx + ty + r * 8, kk = by + tx;
        float v = t[tx][ty + r * 8];                  // = W[kk][n]
        __nv_bfloat16 h = __float2bfloat16_rn(v);
        g_wthi[(size_t)n * Dd + kk] = h;
        g_wtlo[(size_t)n * Dd + kk] = __float2bfloat16_rn(v - __bfloat162float(h));
    }
}

// ===========================================================================
// tcgen05 bf16x3 GEMM, 128(M) x 128(N), TMA-fed, 3 stages of K=64 (64 KB each).
// Warp 0 drives TMA + MMA via mbarriers; 8 warps do the epilogue.
// ===========================================================================
constexpr int TBM = 128, TBN = 128;
constexpr int T_KITERS = Dd / 64;                    // 8
constexpr int TILE_B = 128 * 64 * 2;                 // 16384 per operand tile
constexpr int T_STAGE_BYTES = 4 * TILE_B;            // 65536
constexpr int T_OFF_MBAR  = 8;                       // full[0..2], empty[0..2]
constexpr int T_OFF_TILES = 1024;
constexpr int T_SMEM_TOTAL = T_OFF_TILES + 3 * T_STAGE_BYTES;       // 197632

#if HAS_TC
constexpr uint32_t T_IDESC =
    (1u << 4) | (1u << 7) | (1u << 10) | ((TBN / 8) << 17) | ((TBM / 16) << 24);

__device__ __forceinline__ uint32_t elect_one_pred() {
    uint32_t pred;
    asm volatile("{\n\t.reg .pred p;\n\telect.sync _|p, 0xFFFFFFFF;\n\t"
                 "selp.b32 %0, 1, 0, p;\n\t}" : "=r"(pred));
    return pred;
}
#define MBARRIER_INIT(addr, cnt) \
    asm volatile("mbarrier.init.shared.b64 [%0], %1;" :: "r"(addr), "r"(cnt) : "memory")
#define MBARRIER_EXPECT_TX(addr, bytes) \
    asm volatile("mbarrier.arrive.expect_tx.shared.b64 _, [%0], %1;" \
                 :: "r"(addr), "r"((uint32_t)(bytes)) : "memory")
#define MBAR_WAIT(addr, parity) do {                                          \
    uint32_t _m = (addr), _p = (parity);                                      \
    asm volatile("{\n\t.reg .pred P1;\n\t"                                    \
        "WAIT_LOOP_%=:\n\t"                                                   \
        "mbarrier.try_wait.parity.acquire.cta.shared::cta.b64 P1, [%0], %1, 0x989680;\n\t" \
        "@P1 bra.uni WAIT_DONE_%=;\n\t"                                       \
        "bra.uni WAIT_LOOP_%=;\n\t"                                           \
        "WAIT_DONE_%=:\n\t}" :: "r"(_m), "r"(_p) : "memory");                 \
} while (0)
#define TMA_LOAD_2D(smem_addr, map_ptr, cx, cy, mbar) \
    asm volatile("cp.async.bulk.tensor.2d.shared::cta.global.tile.mbarrier::complete_tx::bytes " \
                 "[%0], [%1, {%2, %3}], [%4];" \
                 :: "r"(smem_addr), "l"(map_ptr), "r"(cx), "r"(cy), "r"(mbar) : "memory")
#define TCGEN05_ALLOC(smem_addr, n) \
    asm volatile("tcgen05.alloc.cta_group::1.sync.aligned.shared::cta.b32 [%0], %1;" \
                 :: "r"(smem_addr), "r"((uint32_t)(n)) : "memory")
#define TCGEN05_DEALLOC(tmem, n) \
    asm volatile("tcgen05.dealloc.cta_group::1.sync.aligned.b32 %0, %1;" \
                 :: "r"(tmem), "r"((uint32_t)(n)))
#define TCGEN05_RELINQ() \
    asm volatile("tcgen05.relinquish_alloc_permit.cta_group::1.sync.aligned;")
#define TCGEN05_COMMIT(mbar) \
    asm volatile("tcgen05.commit.cta_group::1.mbarrier::arrive::one.shared::cluster.b64 [%0];" \
                 :: "r"(mbar) : "memory")
#define TCGEN05_FENCE_AFTER() \
    asm volatile("tcgen05.fence::after_thread_sync;" ::: "memory")
#define TCGEN05_FENCE_BEFORE() \
    asm volatile("tcgen05.fence::before_thread_sync;" ::: "memory")
#define TCGEN05_WAIT_LD() \
    asm volatile("tcgen05.wait::ld.sync.aligned;" ::: "memory")
#define MMA_BF16_SS(dtmem, adesc, bdesc, idesc, enable) do {                  \
    uint32_t _e = (enable); uint32_t _z = 0;                                  \
    asm volatile("{\n\t.reg .pred p;\n\tsetp.ne.u32 p, %5, 0;\n\t"            \
        "tcgen05.mma.cta_group::1.kind::f16 [%0], %1, %2, %3, {%4,%4,%4,%4}, p;\n\t}" \
        :: "r"(dtmem), "l"(adesc), "l"(bdesc), "r"(idesc), "r"(_z), "r"(_e)   \
        : "memory");                                                          \
} while (0)
#define TCGEN05_LD_X32(r, tmem_addr) \
    asm volatile( \
        "tcgen05.ld.sync.aligned.32x32b.x32.b32 " \
        "{%0, %1, %2, %3, %4, %5, %6, %7, %8, %9, %10, %11, %12, %13, %14, %15, " \
        " %16, %17, %18, %19, %20, %21, %22, %23, %24, %25, %26, %27, %28, %29, %30, %31}, [%32];" \
        : "=r"((r)[0]),  "=r"((r)[1]),  "=r"((r)[2]),  "=r"((r)[3]),  \
          "=r"((r)[4]),  "=r"((r)[5]),  "=r"((r)[6]),  "=r"((r)[7]),  \
          "=r"((r)[8]),  "=r"((r)[9]),  "=r"((r)[10]), "=r"((r)[11]), \
          "=r"((r)[12]), "=r"((r)[13]), "=r"((r)[14]), "=r"((r)[15]), \
          "=r"((r)[16]), "=r"((r)[17]), "=r"((r)[18]), "=r"((r)[19]), \
          "=r"((r)[20]), "=r"((r)[21]), "=r"((r)[22]), "=r"((r)[23]), \
          "=r"((r)[24]), "=r"((r)[25]), "=r"((r)[26]), "=r"((r)[27]), \
          "=r"((r)[28]), "=r"((r)[29]), "=r"((r)[30]), "=r"((r)[31]) \
        : "r"(tmem_addr))

static constexpr uint64_t DESC_BASE_SW128 =
    (uint64_t(2) << 61) | (uint64_t(1) << 46) | (uint64_t(64) << 32) | (uint64_t(1) << 16);
__device__ __forceinline__ uint64_t make_desc(uint32_t addr) {
    return DESC_BASE_SW128 | ((uint64_t)(addr >> 4) & 0x3FFF);
}
#endif  // HAS_TC

template <int STAGE>
__global__ void __launch_bounds__(256, 1) gemm_tc(
    const float* __restrict__ bias, float* __restrict__ out,
    const __grid_constant__ CUtensorMap mAhi, const __grid_constant__ CUtensorMap mAlo,
    const __grid_constant__ CUtensorMap mBhi, const __grid_constant__ CUtensorMap mBlo)
{
#if HAS_TC
    extern __shared__ char smem[];
    uint32_t sb = smem_u32(smem);
    const int tid = threadIdx.x;
    const int wid = tid >> 5, lid = tid & 31;
    const int z  = blockIdx.z;
    const int m0 = blockIdx.y * TBM, n0 = blockIdx.x * TBN;

    const int ay0 = z * Np + m0;
    const int by0 = (STAGE == 1) ? n0 : z * Np + n0;

    const uint32_t full0  = sb + T_OFF_MBAR;        // full[s]  = +s*8
    const uint32_t empty0 = sb + T_OFF_MBAR + 24;   // empty[s] = +24+s*8

    if (tid == 0) {
        #pragma unroll
        for (int s = 0; s < 3; s++) {
            MBARRIER_INIT(full0  + s * 8, 1);       // expect_tx arrival
            MBARRIER_INIT(empty0 + s * 8, 1);       // tcgen05.commit arrival
        }
    }
    if (wid == 0) TCGEN05_ALLOC(sb, 128);
    __syncthreads();
    uint32_t tmem;
    asm volatile("ld.shared.b32 %0, [%1];" : "=r"(tmem) : "r"(sb));
    if (wid == 0) TCGEN05_RELINQ();
    __syncthreads();

    if (wid == 0) {
        const uint32_t epred = elect_one_pred();
        auto issue_stage = [&](int k) {     // load k-iter k into stage k%3
            if (epred) {
                uint32_t stg = sb + T_OFF_TILES + (k % 3) * T_STAGE_BYTES;
                int kx = k * 64;
                uint32_t fb = full0 + (k % 3) * 8;
                MBARRIER_EXPECT_TX(fb, T_STAGE_BYTES);
                TMA_LOAD_2D(stg,              &mAhi, kx, ay0, fb);
                TMA_LOAD_2D(stg + TILE_B,     &mAlo, kx, ay0, fb);
                TMA_LOAD_2D(stg + 2 * TILE_B, &mBhi, kx, by0, fb);
                TMA_LOAD_2D(stg + 3 * TILE_B, &mBlo, kx, by0, fb);
            }
        };

        issue_stage(0); issue_stage(1); issue_stage(2);

        for (int k = 0; k < T_KITERS; k++) {
            MBAR_WAIT(full0 + (k % 3) * 8, (k / 3) & 1);
            if (epred) {
                uint32_t stg = sb + T_OFF_TILES + (k % 3) * T_STAGE_BYTES;
                uint64_t dAh = make_desc(stg);
                uint64_t dAl = make_desc(stg + TILE_B);
                uint64_t dBh = make_desc(stg + 2 * TILE_B);
                uint64_t dBl = make_desc(stg + 3 * TILE_B);
                #pragma unroll
                for (int s = 0; s < 4; s++) {             // four K=16 steps
                    uint64_t o = (uint64_t)(s * 2);
                    MMA_BF16_SS(tmem, dAh + o, dBh + o, T_IDESC, (k == 0 && s == 0) ? 0u : 1u);
                    MMA_BF16_SS(tmem, dAh + o, dBl + o, T_IDESC, 1u);
                    MMA_BF16_SS(tmem, dAl + o, dBh + o, T_IDESC, 1u);
                }
                TCGEN05_COMMIT(empty0 + (k % 3) * 8);
            }
            if (k + 3 < T_KITERS) {
                // stage k%3 refilled next: wait its MMAs (commit k) drained
                MBAR_WAIT(empty0 + (k % 3) * 8, (k / 3) & 1);
                issue_stage(k + 3);
            }
        }
        // commit k=7 = 3rd completion on empty[1] -> parity 0
        MBAR_WAIT(empty0 + 1 * 8, 0);
    }

    __syncthreads();            // all warps see the final accumulator
    TCGEN05_FENCE_AFTER();

    // Epilogue: 8 warps. Warps 0-3 -> cols [0,64), warps 4-7 -> cols [64,128).
    {
        const int half = wid >> 2;
        const int gi   = m0 + (wid & 3) * 32 + lid;
        const int cbase = half * 64;
        if (STAGE == 1) {
            size_t base = ((size_t)z * Np + gi) * Dd + n0 + cbase;
            #pragma unroll
            for (int c0 = 0; c0 < 64; c0 += 32) {
                uint32_t r[32];
                TCGEN05_LD_X32(r, tmem + cbase + c0);
                TCGEN05_WAIT_LD();
                __align__(16) __nv_bfloat16 hs[32], ls[32];
                #pragma unroll
                for (int c = 0; c < 32; c++) {
                    float v = __uint_as_float(r[c]);
                    __nv_bfloat16 hh = __float2bfloat16_rn(v);
                    hs[c] = hh;
                    ls[c] = __float2bfloat16_rn(v - __bfloat162float(hh));
                }
                uint4* dh = reinterpret_cast<uint4*>(g_xwhi + base + c0);
                uint4* dl = reinterpret_cast<uint4*>(g_xwlo + base + c0);
                const uint4* sh = reinterpret_cast<const uint4*>(hs);
                const uint4* sl = reinterpret_cast<const uint4*>(ls);
                #pragma unroll
                for (int q = 0; q < 4; q++) { dh[q] = sh[q]; dl[q] = sl[q]; }
            }
        } else {
            const float bv = *bias;
            size_t base = ((size_t)z * Np + gi) * Np + n0 + cbase;
            #pragma unroll
            for (int c0 = 0; c0 < 64; c0 += 32) {
                uint32_t r[32];
                TCGEN05_LD_X32(r, tmem + cbase + c0);
                TCGEN05_WAIT_LD();
                __align__(16) float vs[32];
                #pragma unroll
                for (int c = 0; c < 32; c++) {
                    int gj = n0 + cbase + c0 + c;
                    float v = __uint_as_float(r[c]) + bv;
                    vs[c] = (gi == gj) ? 0.0f : v;
                }
                float4* d = reinterpret_cast<float4*>(out + base + c0);
                const float4* s = reinterpret_cast<const float4*>(vs);
                #pragma unroll
                for (int q = 0; q < 8; q++) d[q] = s[q];
            }
        }
        TCGEN05_FENCE_BEFORE();
    }
    __syncthreads();
    if (wid == 0) TCGEN05_DEALLOC(tmem, 128);
#endif  // HAS_TC
}

// ---------------------------------------------------------------------------
typedef CUresult (*cuTensorMapEncodeTiled_t)(
    CUtensorMap*, CUtensorMapDataType, cuuint32_t, void*,
    const cuuint64_t*, const cuuint64_t*, const cuuint32_t*, const cuuint32_t*,
    CUtensorMapInterleave, CUtensorMapSwizzle, CUtensorMapL2promotion,
    CUtensorMapFloatOOBfill);

extern "C" void kernel_launch(void* const* d_in, const int* in_sizes, int n_in,
                              void* d_out, int out_size) {
    const float* X    = (const float*)d_in[0];   // (32, 512, 512)
    const float* W    = (const float*)d_in[1];   // (512, 512)
    const float* bias = (const float*)d_in[2];   // scalar
    float* out = (float*)d_out;                  // (32, 512, 512)

    cudaFuncSetAttribute(gemm_tc<1>, cudaFuncAttributeMaxDynamicSharedMemorySize, T_SMEM_TOTAL);
    cudaFuncSetAttribute(gemm_tc<2>, cudaFuncAttributeMaxDynamicSharedMemorySize, T_SMEM_TOTAL);

    // Driver entry point via runtime (no -lcuda link dependency).
    cuTensorMapEncodeTiled_t enc = nullptr;
    cudaDriverEntryPointQueryResult qr;
    cudaGetDriverEntryPoint("cuTensorMapEncodeTiled", (void**)&enc,
                            cudaEnableDefault, &qr);

    void *p_xhi, *p_xlo, *p_wthi, *p_wtlo, *p_xwhi, *p_xwlo;
    cudaGetSymbolAddress(&p_xhi,  g_xhi);
    cudaGetSymbolAddress(&p_xlo,  g_xlo);
    cudaGetSymbolAddress(&p_wthi, g_wthi);
    cudaGetSymbolAddress(&p_wtlo, g_wtlo);
    cudaGetSymbolAddress(&p_xwhi, g_xwhi);
    cudaGetSymbolAddress(&p_xwlo, g_xwlo);

    auto make2d = [&](void* base, uint64_t rows) {
        CUtensorMap m{};
        cuuint64_t dims[2]    = {(cuuint64_t)Dd, rows};   // inner = 512 bf16
        cuuint64_t strides[1] = {(cuuint64_t)Dd * 2};     // 1024 B row pitch
        cuuint32_t box[2]     = {64, 128};                // 128B x 128 rows
        cuuint32_t es[2]      = {1, 1};
        enc(&m, CU_TENSOR_MAP_DATA_TYPE_BFLOAT16, 2, base, dims, strides, box, es,
            CU_TENSOR_MAP_INTERLEAVE_NONE, CU_TENSOR_MAP_SWIZZLE_128B,
            CU_TENSOR_MAP_L2_PROMOTION_L2_128B, CU_TENSOR_MAP_FLOAT_OOB_FILL_NONE);
        return m;
    };

    const uint64_t XROWS = (uint64_t)Bb * Np;
    CUtensorMap m_xhi  = make2d(p_xhi,  XROWS);
    CUtensorMap m_xlo  = make2d(p_xlo,  XROWS);
    CUtensorMap m_wthi = make2d(p_wthi, Dd);
    CUtensorMap m_wtlo = make2d(p_wtlo, Dd);
    CUtensorMap m_xwhi = make2d(p_xwhi, XROWS);
    CUtensorMap m_xwlo = make2d(p_xwlo, XROWS);

    conv_w_kernel<<<dim3(16, 16), dim3(32, 8)>>>(W);
    conv_x_kernel<<<(Bb * Np * Dd) / 4 / 256, 256>>>((const float4*)X);

    dim3 grid(Np / TBN, Np / TBM, Bb);   // (4, 4, 32) = 512 CTAs
    gemm_tc<1><<<grid, 256, T_SMEM_TOTAL>>>(bias, out, m_xhi, m_xlo, m_wthi, m_wtlo);
    gemm_tc<2><<<grid, 256, T_SMEM_TOTAL>>>(bias, out, m_xwhi, m_xwlo, m_xhi, m_xlo);
}

// round 13
// speedup vs baseline: 1.2378x; 1.2378x over previous
#include <cuda_runtime.h>
#include <cuda.h>
#include <cuda_bf16.h>
#include <cstdint>

// tcgen05 exists only in the compute_103a pass; plain sm_103 compiles empty stubs.
#if defined(__CUDA_ARCH__) && defined(__CUDA_ARCH_FEAT_SM103_ALL)
#define HAS_TC 1
#else
#define HAS_TC 0
#endif

constexpr int Bb = 32, Np = 512, Dd = 512;

// ---------------- scratch (__device__ globals; alloc-free rule) -------------
__device__ __align__(1024) __nv_bfloat16 g_xhi [(size_t)Bb * Np * Dd];
__device__ __align__(1024) __nv_bfloat16 g_xlo [(size_t)Bb * Np * Dd];
__device__ __align__(1024) __nv_bfloat16 g_wthi[(size_t)Dd * Dd];
__device__ __align__(1024) __nv_bfloat16 g_wtlo[(size_t)Dd * Dd];
__device__ __align__(1024) __nv_bfloat16 g_xwhi[(size_t)Bb * Np * Dd];
__device__ __align__(1024) __nv_bfloat16 g_xwlo[(size_t)Bb * Np * Dd];

// ---------------- common helpers -------------------------------------------
__device__ __forceinline__ uint32_t smem_u32(const void* p) {
    uint32_t a;
    asm("{ .reg .u64 t; cvta.to.shared.u64 t, %1; cvt.u32.u64 %0, t; }"
        : "=r"(a) : "l"(p));
    return a;
}

// ---------------- conversion kernels ---------------------------------------
__global__ __launch_bounds__(256) void conv_x_kernel(const float4* __restrict__ X) {
    size_t i = (size_t)blockIdx.x * 256 + threadIdx.x;
    float4 v = X[i];
    union { __nv_bfloat16 b[4]; uint2 u; } H, L;
    const float* f = &v.x;
    #pragma unroll
    for (int j = 0; j < 4; j++) {
        __nv_bfloat16 h = __float2bfloat16_rn(f[j]);
        H.b[j] = h;
        L.b[j] = __float2bfloat16_rn(f[j] - __bfloat162float(h));
    }
    reinterpret_cast<uint2*>(g_xhi)[i] = H.u;
    reinterpret_cast<uint2*>(g_xlo)[i] = L.u;
}

__global__ __launch_bounds__(256) void conv_w_kernel(const float* __restrict__ W) {
    __shared__ float t[32][33];
    int tx = threadIdx.x, ty = threadIdx.y;          // 32 x 8
    int bx = blockIdx.x * 32, by = blockIdx.y * 32;  // bx: n-block, by: k-block
    #pragma unroll
    for (int r = 0; r < 4; r++)
        t[ty + r * 8][tx] = W[(size_t)(by + ty + r * 8) * Dd + bx + tx];
    __syncthreads();
    #pragma unroll
    for (int r = 0; r < 4; r++) {
        int n = bx + ty + r * 8, kk = by + tx;
        float v = t[tx][ty + r * 8];                  // = W[kk][n]
        __nv_bfloat16 h = __float2bfloat16_rn(v);
        g_wthi[(size_t)n * Dd + kk] = h;
        g_wtlo[(size_t)n * Dd + kk] = __float2bfloat16_rn(v - __bfloat162float(h));
    }
}

// ===========================================================================
// tcgen05 bf16x3 GEMM, 128(M) x 256(N), TMA-fed, SW64 tiles, K=32 stages.
// 2 stages x 48KB = 99KB smem/CTA -> 2 CTAs per SM (single wave, latency
// hidden by two independent TMA/MMA streams per SM).
// ===========================================================================
constexpr int TBM = 128, TBN = 256;
constexpr int NITER = Dd / 32;                       // 16
constexpr int A_T = TBM * 32 * 2;                    // 8192  (128 rows x 64B)
constexpr int B_T = TBN * 32 * 2;                    // 16384 (256 rows x 64B)
constexpr int T_STAGE_BYTES = 2 * A_T + 2 * B_T;     // 49152
constexpr int T_OFF_MBAR  = 8;                       // full[0..1], empty[0..1]
constexpr int T_OFF_TILES = 1024;
constexpr int T_SMEM_TOTAL = T_OFF_TILES + 2 * T_STAGE_BYTES;   // 99328

#if HAS_TC
constexpr uint32_t T_IDESC =
    (1u << 4) | (1u << 7) | (1u << 10) | ((TBN / 8) << 17) | ((TBM / 16) << 24);

__device__ __forceinline__ uint32_t elect_one_pred() {
    uint32_t pred;
    asm volatile("{\n\t.reg .pred p;\n\telect.sync _|p, 0xFFFFFFFF;\n\t"
                 "selp.b32 %0, 1, 0, p;\n\t}" : "=r"(pred));
    return pred;
}
#define MBARRIER_INIT(addr, cnt) \
    asm volatile("mbarrier.init.shared.b64 [%0], %1;" :: "r"(addr), "r"(cnt) : "memory")
#define MBARRIER_EXPECT_TX(addr, bytes) \
    asm volatile("mbarrier.arrive.expect_tx.shared.b64 _, [%0], %1;" \
                 :: "r"(addr), "r"((uint32_t)(bytes)) : "memory")
#define MBAR_WAIT(addr, parity) do {                                          \
    uint32_t _m = (addr), _p = (parity);                                      \
    asm volatile("{\n\t.reg .pred P1;\n\t"                                    \
        "WAIT_LOOP_%=:\n\t"                                                   \
        "mbarrier.try_wait.parity.acquire.cta.shared::cta.b64 P1, [%0], %1, 0x989680;\n\t" \
        "@P1 bra.uni WAIT_DONE_%=;\n\t"                                       \
        "bra.uni WAIT_LOOP_%=;\n\t"                                           \
        "WAIT_DONE_%=:\n\t}" :: "r"(_m), "r"(_p) : "memory");                 \
} while (0)
#define TMA_LOAD_2D(smem_addr, map_ptr, cx, cy, mbar) \
    asm volatile("cp.async.bulk.tensor.2d.shared::cta.global.tile.mbarrier::complete_tx::bytes " \
                 "[%0], [%1, {%2, %3}], [%4];" \
                 :: "r"(smem_addr), "l"(map_ptr), "r"(cx), "r"(cy), "r"(mbar) : "memory")
#define TCGEN05_ALLOC(smem_addr, n) \
    asm volatile("tcgen05.alloc.cta_group::1.sync.aligned.shared::cta.b32 [%0], %1;" \
                 :: "r"(smem_addr), "r"((uint32_t)(n)) : "memory")
#define TCGEN05_DEALLOC(tmem, n) \
    asm volatile("tcgen05.dealloc.cta_group::1.sync.aligned.b32 %0, %1;" \
                 :: "r"(tmem), "r"((uint32_t)(n)))
#define TCGEN05_RELINQ() \
    asm volatile("tcgen05.relinquish_alloc_permit.cta_group::1.sync.aligned;")
#define TCGEN05_COMMIT(mbar) \
    asm volatile("tcgen05.commit.cta_group::1.mbarrier::arrive::one.shared::cluster.b64 [%0];" \
                 :: "r"(mbar) : "memory")
#define TCGEN05_FENCE_AFTER() \
    asm volatile("tcgen05.fence::after_thread_sync;" ::: "memory")
#define TCGEN05_FENCE_BEFORE() \
    asm volatile("tcgen05.fence::before_thread_sync;" ::: "memory")
#define TCGEN05_WAIT_LD() \
    asm volatile("tcgen05.wait::ld.sync.aligned;" ::: "memory")
#define MMA_BF16_SS(dtmem, adesc, bdesc, idesc, enable) do {                  \
    uint32_t _e = (enable); uint32_t _z = 0;                                  \
    asm volatile("{\n\t.reg .pred p;\n\tsetp.ne.u32 p, %5, 0;\n\t"            \
        "tcgen05.mma.cta_group::1.kind::f16 [%0], %1, %2, %3, {%4,%4,%4,%4}, p;\n\t}" \
        :: "r"(dtmem), "l"(adesc), "l"(bdesc), "r"(idesc), "r"(_z), "r"(_e)   \
        : "memory");                                                          \
} while (0)
#define TCGEN05_LD_X32(r, tmem_addr) \
    asm volatile( \
        "tcgen05.ld.sync.aligned.32x32b.x32.b32 " \
        "{%0, %1, %2, %3, %4, %5, %6, %7, %8, %9, %10, %11, %12, %13, %14, %15, " \
        " %16, %17, %18, %19, %20, %21, %22, %23, %24, %25, %26, %27, %28, %29, %30, %31}, [%32];" \
        : "=r"((r)[0]),  "=r"((r)[1]),  "=r"((r)[2]),  "=r"((r)[3]),  \
          "=r"((r)[4]),  "=r"((r)[5]),  "=r"((r)[6]),  "=r"((r)[7]),  \
          "=r"((r)[8]),  "=r"((r)[9]),  "=r"((r)[10]), "=r"((r)[11]), \
          "=r"((r)[12]), "=r"((r)[13]), "=r"((r)[14]), "=r"((r)[15]), \
          "=r"((r)[16]), "=r"((r)[17]), "=r"((r)[18]), "=r"((r)[19]), \
          "=r"((r)[20]), "=r"((r)[21]), "=r"((r)[22]), "=r"((r)[23]), \
          "=r"((r)[24]), "=r"((r)[25]), "=r"((r)[26]), "=r"((r)[27]), \
          "=r"((r)[28]), "=r"((r)[29]), "=r"((r)[30]), "=r"((r)[31]) \
        : "r"(tmem_addr))

// K-major SW64 descriptor: layout=4, version=1, SBO=32 (8 rows x 64B = 512B/16),
// LBO=1 (16B). SW64 atom = 8 rows x 64 bytes (matches TMA SWIZZLE_64B).
static constexpr uint64_t DESC_BASE_SW64 =
    (uint64_t(4) << 61) | (uint64_t(1) << 46) | (uint64_t(32) << 32) | (uint64_t(1) << 16);
__device__ __forceinline__ uint64_t make_desc64(uint32_t addr) {
    return DESC_BASE_SW64 | ((uint64_t)(addr >> 4) & 0x3FFF);
}
#endif  // HAS_TC

template <int STAGE>
__global__ void __launch_bounds__(256, 2) gemm_tc(
    const float* __restrict__ bias, float* __restrict__ out,
    const __grid_constant__ CUtensorMap mAhi, const __grid_constant__ CUtensorMap mAlo,
    const __grid_constant__ CUtensorMap mBhi, const __grid_constant__ CUtensorMap mBlo)
{
#if HAS_TC
    extern __shared__ char smem[];
    uint32_t sb = smem_u32(smem);
    const int tid = threadIdx.x;
    const int wid = tid >> 5, lid = tid & 31;
    const int z  = blockIdx.z;
    const int m0 = blockIdx.y * TBM, n0 = blockIdx.x * TBN;

    const int ay0 = z * Np + m0;
    const int by0 = (STAGE == 1) ? n0 : z * Np + n0;

    const uint32_t full0  = sb + T_OFF_MBAR;        // full[s]  = +s*8
    const uint32_t empty0 = sb + T_OFF_MBAR + 16;   // empty[s] = +16+s*8

    if (tid == 0) {
        #pragma unroll
        for (int s = 0; s < 2; s++) {
            MBARRIER_INIT(full0  + s * 8, 1);       // expect_tx arrival
            MBARRIER_INIT(empty0 + s * 8, 1);       // tcgen05.commit arrival
        }
    }
    if (wid == 0) TCGEN05_ALLOC(sb, 256);
    __syncthreads();
    uint32_t tmem;
    asm volatile("ld.shared.b32 %0, [%1];" : "=r"(tmem) : "r"(sb));
    if (wid == 0) TCGEN05_RELINQ();
    __syncthreads();

    if (wid == 0) {
        // ---- mainloop driver: whole warp stays converged; lane0 issues ----
        const uint32_t epred = elect_one_pred();
        auto issue_stage = [&](int k) {     // load k-iter k (K=32) into stage k&1
            if (epred) {
                uint32_t stg = sb + T_OFF_TILES + (k & 1) * T_STAGE_BYTES;
                int kx = k * 32;            // element coord along K
                uint32_t fb = full0 + (k & 1) * 8;
                MBARRIER_EXPECT_TX(fb, T_STAGE_BYTES);
                TMA_LOAD_2D(stg,                 &mAhi, kx, ay0, fb);
                TMA_LOAD_2D(stg + A_T,           &mAlo, kx, ay0, fb);
                TMA_LOAD_2D(stg + 2 * A_T,       &mBhi, kx, by0, fb);
                TMA_LOAD_2D(stg + 2 * A_T + B_T, &mBlo, kx, by0, fb);
            }
        };

        issue_stage(0);
        issue_stage(1);

        for (int k = 0; k < NITER; k++) {
            MBAR_WAIT(full0 + (k & 1) * 8, (k >> 1) & 1);
            if (epred) {
                uint32_t stg = sb + T_OFF_TILES + (k & 1) * T_STAGE_BYTES;
                uint64_t dAh = make_desc64(stg);
                uint64_t dAl = make_desc64(stg + A_T);
                uint64_t dBh = make_desc64(stg + 2 * A_T);
                uint64_t dBl = make_desc64(stg + 2 * A_T + B_T);
                #pragma unroll
                for (int s = 0; s < 2; s++) {             // two K=16 steps
                    uint64_t o = (uint64_t)(s * 2);       // +32B within 64B rows
                    MMA_BF16_SS(tmem, dAh + o, dBh + o, T_IDESC, (k == 0 && s == 0) ? 0u : 1u);
                    MMA_BF16_SS(tmem, dAh + o, dBl + o, T_IDESC, 1u);
                    MMA_BF16_SS(tmem, dAl + o, dBh + o, T_IDESC, 1u);
                }
                TCGEN05_COMMIT(empty0 + (k & 1) * 8);
            }
            if (k + 2 < NITER) {
                // stage k&1 refilled next: wait its MMAs (commit k) drained
                MBAR_WAIT(empty0 + (k & 1) * 8, (k >> 1) & 1);
                issue_stage(k + 2);
            }
        }
        // commit k=15 = 8th completion on empty[1] -> parity (15>>1)&1 = 1
        MBAR_WAIT(empty0 + 8, 1);
    }

    __syncthreads();            // all warps see the final accumulator
    TCGEN05_FENCE_AFTER();

    // Epilogue: 8 warps. Warps 0-3 -> cols [0,128), warps 4-7 -> cols [128,256).
    {
        const int half = wid >> 2;
        const int gi   = m0 + (wid & 3) * 32 + lid;
        const int cbase = half * 128;
        if (STAGE == 1) {
            size_t base = ((size_t)z * Np + gi) * Dd + n0 + cbase;
            #pragma unroll
            for (int c0 = 0; c0 < 128; c0 += 32) {
                uint32_t r[32];
                TCGEN05_LD_X32(r, tmem + cbase + c0);
                TCGEN05_WAIT_LD();
                __align__(16) __nv_bfloat16 hs[32], ls[32];
                #pragma unroll
                for (int c = 0; c < 32; c++) {
                    float v = __uint_as_float(r[c]);
                    __nv_bfloat16 hh = __float2bfloat16_rn(v);
                    hs[c] = hh;
                    ls[c] = __float2bfloat16_rn(v - __bfloat162float(hh));
                }
                uint4* dh = reinterpret_cast<uint4*>(g_xwhi + base + c0);
                uint4* dl = reinterpret_cast<uint4*>(g_xwlo + base + c0);
                const uint4* sh = reinterpret_cast<const uint4*>(hs);
                const uint4* sl = reinterpret_cast<const uint4*>(ls);
                #pragma unroll
                for (int q = 0; q < 4; q++) { dh[q] = sh[q]; dl[q] = sl[q]; }
            }
        } else {
            const float bv = *bias;
            size_t base = ((size_t)z * Np + gi) * Np + n0 + cbase;
            #pragma unroll
            for (int c0 = 0; c0 < 128; c0 += 32) {
                uint32_t r[32];
                TCGEN05_LD_X32(r, tmem + cbase + c0);
                TCGEN05_WAIT_LD();
                __align__(16) float vs[32];
                #pragma unroll
                for (int c = 0; c < 32; c++) {
                    int gj = n0 + cbase + c0 + c;
                    float v = __uint_as_float(r[c]) + bv;
                    vs[c] = (gi == gj) ? 0.0f : v;
                }
                float4* d = reinterpret_cast<float4*>(out + base + c0);
                const float4* s = reinterpret_cast<const float4*>(vs);
                #pragma unroll
                for (int q = 0; q < 8; q++) d[q] = s[q];
            }
        }
        TCGEN05_FENCE_BEFORE();
    }
    __syncthreads();
    if (wid == 0) TCGEN05_DEALLOC(tmem, 256);
#endif  // HAS_TC
}

// ---------------------------------------------------------------------------
typedef CUresult (*cuTensorMapEncodeTiled_t)(
    CUtensorMap*, CUtensorMapDataType, cuuint32_t, void*,
    const cuuint64_t*, const cuuint64_t*, const cuuint32_t*, const cuuint32_t*,
    CUtensorMapInterleave, CUtensorMapSwizzle, CUtensorMapL2promotion,
    CUtensorMapFloatOOBfill);

extern "C" void kernel_launch(void* const* d_in, const int* in_sizes, int n_in,
                              void* d_out, int out_size) {
    const float* X    = (const float*)d_in[0];   // (32, 512, 512)
    const float* W    = (const float*)d_in[1];   // (512, 512)
    const float* bias = (const float*)d_in[2];   // scalar
    float* out = (float*)d_out;                  // (32, 512, 512)

    cudaFuncSetAttribute(gemm_tc<1>, cudaFuncAttributeMaxDynamicSharedMemorySize, T_SMEM_TOTAL);
    cudaFuncSetAttribute(gemm_tc<2>, cudaFuncAttributeMaxDynamicSharedMemorySize, T_SMEM_TOTAL);

    // Driver entry point via runtime (no -lcuda link dependency).
    cuTensorMapEncodeTiled_t enc = nullptr;
    cudaDriverEntryPointQueryResult qr;
    cudaGetDriverEntryPoint("cuTensorMapEncodeTiled", (void**)&enc,
                            cudaEnableDefault, &qr);

    void *p_xhi, *p_xlo, *p_wthi, *p_wtlo, *p_xwhi, *p_xwlo;
    cudaGetSymbolAddress(&p_xhi,  g_xhi);
    cudaGetSymbolAddress(&p_xlo,  g_xlo);
    cudaGetSymbolAddress(&p_wthi, g_wthi);
    cudaGetSymbolAddress(&p_wtlo, g_wtlo);
    cudaGetSymbolAddress(&p_xwhi, g_xwhi);
    cudaGetSymbolAddress(&p_xwlo, g_xwlo);

    auto make2d = [&](void* base, uint64_t rows, uint32_t boxRows) {
        CUtensorMap m{};
        cuuint64_t dims[2]    = {(cuuint64_t)Dd, rows};   // inner = 512 bf16
        cuuint64_t strides[1] = {(cuuint64_t)Dd * 2};     // 1024 B row pitch
        cuuint32_t box[2]     = {32, boxRows};            // 32 bf16 = 64B = SW64
        cuuint32_t es[2]      = {1, 1};
        enc(&m, CU_TENSOR_MAP_DATA_TYPE_BFLOAT16, 2, base, dims, strides, box, es,
            CU_TENSOR_MAP_INTERLEAVE_NONE, CU_TENSOR_MAP_SWIZZLE_64B,
            CU_TENSOR_MAP_L2_PROMOTION_L2_128B, CU_TENSOR_MAP_FLOAT_OOB_FILL_NONE);
        return m;
    };

    const uint64_t XROWS = (uint64_t)Bb * Np;
    CUtensorMap m_xhiA  = make2d(p_xhi,  XROWS, 128);
    CUtensorMap m_xloA  = make2d(p_xlo,  XROWS, 128);
    CUtensorMap m_wthiB = make2d(p_wthi, Dd,    256);
    CUtensorMap m_wtloB = make2d(p_wtlo, Dd,    256);
    CUtensorMap m_xwhiA = make2d(p_xwhi, XROWS, 128);
    CUtensorMap m_xwloA = make2d(p_xwlo, XROWS, 128);
    CUtensorMap m_xhiB  = make2d(p_xhi,  XROWS, 256);
    CUtensorMap m_xloB  = make2d(p_xlo,  XROWS, 256);

    conv_w_kernel<<<dim3(16, 16), dim3(32, 8)>>>(W);
    conv_x_kernel<<<(Bb * Np * Dd) / 4 / 256, 256>>>((const float4*)X);

    dim3 grid(Np / TBN, Np / TBM, Bb);   // (2, 4, 32) = 256 CTAs, 2 per SM
    gemm_tc<1><<<grid, 256, T_SMEM_TOTAL>>>(bias, out, m_xhiA, m_xloA, m_wthiB, m_wtloB);
    gemm_tc<2><<<grid, 256, T_SMEM_TOTAL>>>(bias, out, m_xwhiA, m_xwloA, m_xhiB, m_xloB);
}